// round 3
// baseline (speedup 1.0000x reference)
#include <cuda_runtime.h>

#define HH 256
#define WW 256
#define BB 2
#define CC 4
#define NROWS (BB*HH)        // 512 blocks, one per (b,h) row
#define NTOT (BB*CC*HH*WW)   // 524288

// Per-block partials (written fresh each run -> no init kernel needed)
__device__ float        g_pA[NROWS];
__device__ float        g_pS[NROWS][CC];
__device__ int          g_pM[NROWS][CC];
__device__ unsigned int g_cnt = 0;       // self-resetting completion counter

// Label fetch handling int64 (shift=1) vs int32 (shift=0) storage.
__device__ __forceinline__ int labAt(const int* __restrict__ y, int shift,
                                     int b, int idx) {
    return y[((b << 16) + idx) << shift];
}

__global__ void __launch_bounds__(256) rw_fused(const int* __restrict__ y,
                                                const float* __restrict__ x,
                                                float* __restrict__ out) {
    __shared__ int   sl[3][WW];          // label rows h-1, h, h+1
    __shared__ int   s_is32;
    __shared__ float swA[8], swS[8][CC];
    __shared__ int   swM[8][CC];
    __shared__ int   s_last;

    const int r = blockIdx.x;            // b*256 + h
    const int b = r >> 8;
    const int h = r & 255;
    const int w = threadIdx.x;

    // ---- dtype sniff: int64 little-endian => high 32-bit words all zero ----
    if (w == 0) s_is32 = 0;
    __syncthreads();
    if (w < 128) {
        int2 v = ((const int2*)y)[w];    // first 1KB, identical for all blocks
        if (v.y != 0) atomicOr(&s_is32, 1);
    }
    __syncthreads();
    const int shift = s_is32 ? 0 : 1;

    // ---- load the 3 label rows into smem ----
    #pragma unroll
    for (int k = 0; k < 3; k++) {
        int hh = h - 1 + k;
        if (hh >= 0 && hh < HH) sl[k][w] = labAt(y, shift, b, hh * WW + w);
    }
    __syncthreads();

    const int L = sl[1][w];

    // ---- d^2 to nearest differing label (ring search, integer-exact) ----
    int best;
    bool ax = (w > 0      && sl[1][w-1] != L) ||
              (w < WW-1   && sl[1][w+1] != L) ||
              (h > 0      && sl[0][w]   != L) ||
              (h < HH-1   && sl[2][w]   != L);
    if (ax) {
        best = 1;
    } else {
        bool dg = false;
        if (h > 0) {
            if (w > 0    && sl[0][w-1] != L) dg = true;
            if (w < WW-1 && sl[0][w+1] != L) dg = true;
        }
        if (h < HH-1) {
            if (w > 0    && sl[2][w-1] != L) dg = true;
            if (w < WW-1 && sl[2][w+1] != L) dg = true;
        }
        best = dg ? 2 : 0x7fffffff;
        // Rare general rings (needs a 3x3 uniform patch: p ~ 4^-8)
        for (int R = 2; R < 512 && R * R < best; R++) {
            int hm = h - R, hp = h + R, wm = w - R, wp = w + R;
            int wlo = wm < 0 ? 0 : wm, whi = wp > WW-1 ? WW-1 : wp;
            if (hm >= 0) {
                for (int ww = wlo; ww <= whi; ww++)
                    if (labAt(y, shift, b, hm * WW + ww) != L) {
                        int dw = ww - w, d2 = R*R + dw*dw;
                        if (d2 < best) best = d2;
                    }
            }
            if (hp <= HH-1) {
                for (int ww = wlo; ww <= whi; ww++)
                    if (labAt(y, shift, b, hp * WW + ww) != L) {
                        int dw = ww - w, d2 = R*R + dw*dw;
                        if (d2 < best) best = d2;
                    }
            }
            int hlo = hm + 1 < 0 ? 0 : hm + 1;
            int hhi = hp - 1 > HH-1 ? HH-1 : hp - 1;
            if (wm >= 0) {
                for (int hh = hlo; hh <= hhi; hh++)
                    if (labAt(y, shift, b, hh * WW + wm) != L) {
                        int dh = hh - h, d2 = R*R + dh*dh;
                        if (d2 < best) best = d2;
                    }
            }
            if (wp <= WW-1) {
                for (int hh = hlo; hh <= hhi; hh++)
                    if (labAt(y, shift, b, hh * WW + wp) != L) {
                        int dh = hh - h, d2 = R*R + dh*dh;
                        if (d2 < best) best = d2;
                    }
            }
        }
    }

    // ---- softmax p_L over C=4 ----
    const int hw = (h << 8) + w;
    float xv[CC], m = -1e30f;
    #pragma unroll
    for (int c = 0; c < CC; c++) {
        xv[c] = x[((b * CC + c) << 16) + hw];
        m = fmaxf(m, xv[c]);
    }
    float s = 0.0f;
    #pragma unroll
    for (int c = 0; c < CC; c++) { xv[c] = __expf(xv[c] - m); s += xv[c]; }
    const float pL = xv[L] / s;

    // ---- per-thread contributions ----
    float A = 1.0f - pL;
    float S[CC]; int M[CC];
    float sd = pL * sqrtf((float)best);
    #pragma unroll
    for (int c = 0; c < CC; c++) { S[c] = (c == L) ? sd : 0.0f;
                                   M[c] = (c == L) ? best : 0; }

    // ---- block reduction (deterministic shuffles) ----
    #pragma unroll
    for (int off = 16; off; off >>= 1) {
        A += __shfl_xor_sync(0xffffffffu, A, off);
        #pragma unroll
        for (int c = 0; c < CC; c++) {
            S[c] += __shfl_xor_sync(0xffffffffu, S[c], off);
            M[c] = max(M[c], __shfl_xor_sync(0xffffffffu, M[c], off));
        }
    }
    int wp = w >> 5;
    if ((w & 31) == 0) {
        swA[wp] = A;
        #pragma unroll
        for (int c = 0; c < CC; c++) { swS[wp][c] = S[c]; swM[wp][c] = M[c]; }
    }
    __syncthreads();
    if (w < 8) {
        A = swA[w];
        #pragma unroll
        for (int c = 0; c < CC; c++) { S[c] = swS[w][c]; M[c] = swM[w][c]; }
        #pragma unroll
        for (int off = 4; off; off >>= 1) {
            A += __shfl_xor_sync(0xffu, A, off);
            #pragma unroll
            for (int c = 0; c < CC; c++) {
                S[c] += __shfl_xor_sync(0xffu, S[c], off);
                M[c] = max(M[c], __shfl_xor_sync(0xffu, M[c], off));
            }
        }
        if (w == 0) {
            g_pA[r] = A;
            #pragma unroll
            for (int c = 0; c < CC; c++) { g_pS[r][c] = S[c]; g_pM[r][c] = M[c]; }
        }
    }

    // ---- last-block-done final reduction ----
    __threadfence();
    if (w == 0) {
        unsigned int old = atomicAdd(&g_cnt, 1u);
        s_last = (old == NROWS - 1);
    }
    __syncthreads();
    if (!s_last) return;

    float a = 0.0f, S8[2*CC] = {0,0,0,0,0,0,0,0};
    int   M8[2*CC] = {0,0,0,0,0,0,0,0};
    for (int i = w; i < NROWS; i += 256) {
        a += __ldcg(&g_pA[i]);
        int bb = i >> 8;
        #pragma unroll
        for (int c = 0; c < CC; c++) {
            S8[bb*CC + c] += __ldcg(&g_pS[i][c]);
            M8[bb*CC + c]  = max(M8[bb*CC + c], __ldcg(&g_pM[i][c]));
        }
    }
    #pragma unroll
    for (int off = 16; off; off >>= 1) {
        a += __shfl_xor_sync(0xffffffffu, a, off);
        #pragma unroll
        for (int k = 0; k < 2*CC; k++) {
            S8[k] += __shfl_xor_sync(0xffffffffu, S8[k], off);
            M8[k] = max(M8[k], __shfl_xor_sync(0xffffffffu, M8[k], off));
        }
    }
    __shared__ float fA[8], fS[8][2*CC];
    __shared__ int   fM[8][2*CC];
    int wp2 = w >> 5;
    if ((w & 31) == 0) {
        fA[wp2] = a;
        #pragma unroll
        for (int k = 0; k < 2*CC; k++) { fS[wp2][k] = S8[k]; fM[wp2][k] = M8[k]; }
    }
    __syncthreads();
    if (w < 8) {
        a = fA[w];
        #pragma unroll
        for (int k = 0; k < 2*CC; k++) { S8[k] = fS[w][k]; M8[k] = fM[w][k]; }
        #pragma unroll
        for (int off = 4; off; off >>= 1) {
            a += __shfl_xor_sync(0xffu, a, off);
            #pragma unroll
            for (int k = 0; k < 2*CC; k++) {
                S8[k] += __shfl_xor_sync(0xffu, S8[k], off);
                M8[k] = max(M8[k], __shfl_xor_sync(0xffu, M8[k], off));
            }
        }
        if (w == 0) {
            float res = a;
            #pragma unroll
            for (int k = 0; k < 2*CC; k++)
                res -= S8[k] / (sqrtf((float)M8[k]) + 1e-15f);
            out[0] = res * (1.0f / (float)NTOT);
            __threadfence();
            g_cnt = 0;                   // reset for next graph replay
        }
    }
}

// ---------------------------------------------------------------------------
extern "C" void kernel_launch(void* const* d_in, const int* in_sizes, int n_in,
                              void* d_out, int out_size) {
    const float* x;
    const void*  y;
    if (in_sizes[0] == NTOT) { x = (const float*)d_in[0]; y = d_in[1]; }
    else                     { x = (const float*)d_in[1]; y = d_in[0]; }

    rw_fused<<<NROWS, 256>>>((const int*)y, x, (float*)d_out);
}

// round 4
// speedup vs baseline: 1.3732x; 1.3732x over previous
#include <cuda_runtime.h>

#define HH 256
#define WW 256
#define BB 2
#define CC 4
#define NROWS (BB*HH)        // 512 blocks, one per (b,h) row
#define NTOT (BB*CC*HH*WW)   // 524288
#define FPS 4096.0f          // fixed-point scale
#define INV_FPS (1.0f/4096.0f)

// Per-block integer partials (written fresh each run -> no init kernel)
__device__ int g_pA[NROWS];
__device__ int g_pS[NROWS][CC];
__device__ int g_pM[NROWS][CC];
__device__ unsigned int g_cnt = 0;   // self-resetting completion counter

__device__ __forceinline__ int labAt(const int* __restrict__ y, int shift,
                                     int b, int idx) {
    return y[((b << 16) + idx) << shift];
}

__global__ void __launch_bounds__(256) rw_fused(const int* __restrict__ y,
                                                const float* __restrict__ x,
                                                float* __restrict__ out) {
    __shared__ int sl[3][WW];
    __shared__ int s_shift;
    __shared__ int sA, sS[CC], sM[CC];
    __shared__ int fA, fS[2*CC], fM[2*CC];
    __shared__ int s_last;

    const int r    = blockIdx.x;     // b*256 + h
    const int b    = r >> 8;
    const int h    = r & 255;
    const int w    = threadIdx.x;
    const int lane = w & 31;
    const int hw   = (h << 8) + w;

    // ---- issue x loads first (independent of everything below) ----
    float xv[CC];
    #pragma unroll
    for (int c = 0; c < CC; c++)
        xv[c] = __ldg(&x[((b * CC + c) << 16) + hw]);

    // ---- cheap dtype sniff (warp 0): int64 LE => odd words all zero ----
    if (w < 32) {
        int odd  = y[2 * w + 1];
        int is64 = __all_sync(0xffffffffu, odd == 0);
        if (w == 0)  { s_shift = is64; sA = 0; }
        if (w < CC)  { sS[w] = 0; sM[w] = 0; }
    }
    __syncthreads();
    const int shift = s_shift;

    // ---- stage 3 label rows in smem ----
    #pragma unroll
    for (int k = 0; k < 3; k++) {
        int hh = h - 1 + k;
        if (hh >= 0 && hh < HH)
            sl[k][w] = labAt(y, shift, b, hh * WW + w);
    }
    __syncthreads();

    const int L = sl[1][w];

    // ---- d^2 to nearest differing label (integer-exact ring search) ----
    int best;
    bool ax = (w > 0      && sl[1][w-1] != L) ||
              (w < WW-1   && sl[1][w+1] != L) ||
              (h > 0      && sl[0][w]   != L) ||
              (h < HH-1   && sl[2][w]   != L);
    if (ax) {
        best = 1;
    } else {
        bool dg = false;
        if (h > 0) {
            if (w > 0    && sl[0][w-1] != L) dg = true;
            if (w < WW-1 && sl[0][w+1] != L) dg = true;
        }
        if (h < HH-1) {
            if (w > 0    && sl[2][w-1] != L) dg = true;
            if (w < WW-1 && sl[2][w+1] != L) dg = true;
        }
        best = dg ? 2 : 0x7fffffff;
        // Rare general rings (needs 3x3 uniform patch: p ~ 4^-8)
        for (int R = 2; R < 512 && R * R < best; R++) {
            int hm = h - R, hp = h + R, wm = w - R, wp = w + R;
            int wlo = wm < 0 ? 0 : wm, whi = wp > WW-1 ? WW-1 : wp;
            if (hm >= 0)
                for (int ww = wlo; ww <= whi; ww++)
                    if (labAt(y, shift, b, hm * WW + ww) != L) {
                        int dw = ww - w, d2 = R*R + dw*dw;
                        if (d2 < best) best = d2;
                    }
            if (hp <= HH-1)
                for (int ww = wlo; ww <= whi; ww++)
                    if (labAt(y, shift, b, hp * WW + ww) != L) {
                        int dw = ww - w, d2 = R*R + dw*dw;
                        if (d2 < best) best = d2;
                    }
            int hlo = hm + 1 < 0 ? 0 : hm + 1;
            int hhi = hp - 1 > HH-1 ? HH-1 : hp - 1;
            if (wm >= 0)
                for (int hh = hlo; hh <= hhi; hh++)
                    if (labAt(y, shift, b, hh * WW + wm) != L) {
                        int dh = hh - h, d2 = R*R + dh*dh;
                        if (d2 < best) best = d2;
                    }
            if (wp <= WW-1)
                for (int hh = hlo; hh <= hhi; hh++)
                    if (labAt(y, shift, b, hh * WW + wp) != L) {
                        int dh = hh - h, d2 = R*R + dh*dh;
                        if (d2 < best) best = d2;
                    }
        }
    }

    // ---- softmax p_L (x already in registers) ----
    float m = fmaxf(fmaxf(xv[0], xv[1]), fmaxf(xv[2], xv[3]));
    float s = 0.0f;
    #pragma unroll
    for (int c = 0; c < CC; c++) { xv[c] = __expf(xv[c] - m); s += xv[c]; }
    const float pL = xv[L] / s;

    // ---- fixed-point per-thread contributions ----
    const int ai = __float2int_rn((1.0f - pL) * FPS);
    const int si = __float2int_rn(pL * sqrtf((float)best) * FPS);

    // ---- warp reduction via REDUX, lane0 -> smem atomics ----
    int wA = __reduce_add_sync(0xffffffffu, ai);
    int wS[CC], wM[CC];
    #pragma unroll
    for (int c = 0; c < CC; c++) {
        wS[c] = __reduce_add_sync(0xffffffffu, (L == c) ? si : 0);
        wM[c] = __reduce_max_sync(0xffffffffu, (L == c) ? best : 0);
    }
    if (lane == 0) {
        atomicAdd(&sA, wA);
        #pragma unroll
        for (int c = 0; c < CC; c++) {
            atomicAdd(&sS[c], wS[c]);
            atomicMax(&sM[c], wM[c]);
        }
    }
    // init tail accumulators while we're here (pre-sync; harmless for all blocks)
    if (w < 2*CC) { fS[w] = 0; fM[w] = 0; }
    if (w == 16)  fA = 0;
    __syncthreads();

    // ---- publish per-block partials; last-block detection ----
    if (w == 0) {
        g_pA[r] = sA;
        #pragma unroll
        for (int c = 0; c < CC; c++) { g_pS[r][c] = sS[c]; g_pM[r][c] = sM[c]; }
        __threadfence();
        unsigned int old = atomicAdd(&g_cnt, 1u);
        s_last = (old == NROWS - 1);
    }
    __syncthreads();
    if (!s_last) return;

    // ---- tail: warp k reduces rows [64k, 64k+64)  (uniform b per warp) ----
    {
        const int wid  = w >> 5;
        const int base = wid * 64;
        const int bb   = base >> 8;
        const int r0   = base + 2 * lane, r1 = r0 + 1;

        int tA = __ldcg(&g_pA[r0]) + __ldcg(&g_pA[r1]);
        int tS[CC], tM[CC];
        #pragma unroll
        for (int c = 0; c < CC; c++) {
            tS[c] = __ldcg(&g_pS[r0][c]) + __ldcg(&g_pS[r1][c]);
            tM[c] = max(__ldcg(&g_pM[r0][c]), __ldcg(&g_pM[r1][c]));
        }
        tA = __reduce_add_sync(0xffffffffu, tA);
        #pragma unroll
        for (int c = 0; c < CC; c++) {
            tS[c] = __reduce_add_sync(0xffffffffu, tS[c]);
            tM[c] = __reduce_max_sync(0xffffffffu, tM[c]);
        }
        if (lane == 0) {
            atomicAdd(&fA, tA);
            #pragma unroll
            for (int c = 0; c < CC; c++) {
                atomicAdd(&fS[bb * CC + c], tS[c]);
                atomicMax(&fM[bb * CC + c], tM[c]);
            }
        }
    }
    __syncthreads();
    if (w == 0) {
        float res = (float)fA * INV_FPS;
        #pragma unroll
        for (int k = 0; k < 2*CC; k++)
            res -= ((float)fS[k] * INV_FPS) / (sqrtf((float)fM[k]) + 1e-15f);
        out[0] = res * (1.0f / (float)NTOT);
        __threadfence();
        g_cnt = 0;                       // reset for next graph replay
    }
}

// ---------------------------------------------------------------------------
extern "C" void kernel_launch(void* const* d_in, const int* in_sizes, int n_in,
                              void* d_out, int out_size) {
    const float* x;
    const void*  y;
    if (in_sizes[0] == NTOT) { x = (const float*)d_in[0]; y = d_in[1]; }
    else                     { x = (const float*)d_in[1]; y = d_in[0]; }

    rw_fused<<<NROWS, 256>>>((const int*)y, x, (float*)d_out);
}